// round 2
// baseline (speedup 1.0000x reference)
#include <cuda_runtime.h>
#include <math.h>

#define BM 64
#define BN 64
#define BK 16

static constexpr int Bsz  = 4;
static constexpr int NH   = 8;
static constexpr int L    = 1025;
static constexpr int HD   = 512;
static constexpr int IND  = 512;
static constexpr int QKVD = 4096;
static constexpr int BH   = Bsz * NH;            // 32
static constexpr int MQ   = Bsz * L;             // 4100 rows for qkv / out proj

static constexpr size_t QSZ  = (size_t)BH * L * HD;      // 16,793,600
static constexpr size_t LSZ  = (size_t)BH * L * L;       // 33,620,000
static constexpr size_t SSZ  = (size_t)Bsz * L * QKVD;   // 16,793,600

__device__ float g_Q[QSZ];
__device__ float g_K[QSZ];
__device__ float g_V[QSZ];
__device__ float g_PQ[QSZ];
__device__ float g_PK[QSZ];
__device__ float g_PV[QSZ];
__device__ float g_logits[LSZ];
__device__ float g_stacked[SSZ];

// ---------------------------------------------------------------------------
// Kernel 1: fused QKV projection.  C[4100,4096] = x[4100,512] * W^T + b
// W is [4096, 512] row-major ([o, i]).  z picks Q/K/V.
// Output written directly into head-major layout [b, n, l, c].
// ---------------------------------------------------------------------------
__global__ __launch_bounds__(256) void k_qkv(
    const float* __restrict__ x,
    const float* __restrict__ Wq, const float* __restrict__ bq,
    const float* __restrict__ Wk, const float* __restrict__ bk,
    const float* __restrict__ Wv, const float* __restrict__ bv)
{
    const float* W; const float* bias; float* out;
    if (blockIdx.z == 0)      { W = Wq; bias = bq; out = g_Q; }
    else if (blockIdx.z == 1) { W = Wk; bias = bk; out = g_K; }
    else                      { W = Wv; bias = bv; out = g_V; }

    __shared__ __align__(16) float As[BK][BM];
    __shared__ __align__(16) float Bs[BK][BN];

    const int tid = threadIdx.x;
    const int tx = tid & 15, ty = tid >> 4;
    const int row0 = blockIdx.y * BM;
    const int col0 = blockIdx.x * BN;
    const int lrow = tid >> 2;
    const int kc   = (tid & 3) << 2;

    float acc[4][4] = {};

    for (int k0 = 0; k0 < IND; k0 += BK) {
        float4 a4 = make_float4(0.f, 0.f, 0.f, 0.f);
        int gr = row0 + lrow;
        if (gr < MQ) a4 = *(const float4*)(x + (size_t)gr * IND + k0 + kc);
        As[kc + 0][lrow] = a4.x; As[kc + 1][lrow] = a4.y;
        As[kc + 2][lrow] = a4.z; As[kc + 3][lrow] = a4.w;

        float4 b4 = *(const float4*)(W + (size_t)(col0 + lrow) * IND + k0 + kc);
        Bs[kc + 0][lrow] = b4.x; Bs[kc + 1][lrow] = b4.y;
        Bs[kc + 2][lrow] = b4.z; Bs[kc + 3][lrow] = b4.w;
        __syncthreads();

#pragma unroll
        for (int kk = 0; kk < BK; kk++) {
            float4 av = *(const float4*)&As[kk][ty << 2];
            float4 bv2 = *(const float4*)&Bs[kk][tx << 2];
            float a[4] = {av.x, av.y, av.z, av.w};
            float b[4] = {bv2.x, bv2.y, bv2.z, bv2.w};
#pragma unroll
            for (int i = 0; i < 4; i++)
#pragma unroll
                for (int j = 0; j < 4; j++) acc[i][j] += a[i] * b[j];
        }
        __syncthreads();
    }

#pragma unroll
    for (int i = 0; i < 4; i++) {
        int m = row0 + (ty << 2) + i;
        if (m >= MQ) continue;
        int bb = m / L, l = m % L;
#pragma unroll
        for (int j = 0; j < 4; j++) {
            int o = col0 + (tx << 2) + j;
            int n = o >> 9, c = o & 511;
            out[(((size_t)(bb * NH + n)) * L + l) * HD + c] = acc[i][j] + bias[o];
        }
    }
}

// ---------------------------------------------------------------------------
// Kernel 2: copy cls tokens (l=0) through the pooler unchanged.
// ---------------------------------------------------------------------------
__global__ __launch_bounds__(256) void k_cls()
{
    int idx = blockIdx.x * blockDim.x + threadIdx.x;   // 3*32*512
    if (idx >= 3 * BH * HD) return;
    int t   = idx / (BH * HD);
    int rem = idx % (BH * HD);
    int bn  = rem / HD;
    int c   = rem % HD;
    size_t off = (size_t)bn * L * HD + c;
    if (t == 0)      g_PQ[off] = g_Q[off];
    else if (t == 1) g_PK[off] = g_K[off];
    else             g_PV[off] = g_V[off];
}

// ---------------------------------------------------------------------------
// Kernel 3: pooler GEMM on spatial tokens.  Per (b,n): [1024,512]*[512,512]^T
// + bias, plus 2D sinusoidal pos-embed fused into PQ epilogue.
// grid = (8, 512, 3): y enumerates 64-row tiles of 32768 spatial rows.
// ---------------------------------------------------------------------------
__global__ __launch_bounds__(256) void k_pool(
    const float* __restrict__ Wpq, const float* __restrict__ bpq,
    const float* __restrict__ Wpk, const float* __restrict__ bpk,
    const float* __restrict__ Wpv, const float* __restrict__ bpv)
{
    const float* src; const float* W; const float* bias; float* dst; bool pos;
    if (blockIdx.z == 0)      { src = g_Q; W = Wpq; bias = bpq; dst = g_PQ; pos = true; }
    else if (blockIdx.z == 1) { src = g_K; W = Wpk; bias = bpk; dst = g_PK; pos = false; }
    else                      { src = g_V; W = Wpv; bias = bpv; dst = g_PV; pos = false; }

    const int bn     = blockIdx.y >> 4;
    const int lstart = (blockIdx.y & 15) * BM;
    const float* A = src + ((size_t)bn * L + 1 + lstart) * HD;

    __shared__ __align__(16) float As[BK][BM];
    __shared__ __align__(16) float Bs[BK][BN];

    const int tid = threadIdx.x;
    const int tx = tid & 15, ty = tid >> 4;
    const int col0 = blockIdx.x * BN;
    const int lrow = tid >> 2;
    const int kc   = (tid & 3) << 2;

    float acc[4][4] = {};

    for (int k0 = 0; k0 < HD; k0 += BK) {
        float4 a4 = *(const float4*)(A + (size_t)lrow * HD + k0 + kc);
        As[kc + 0][lrow] = a4.x; As[kc + 1][lrow] = a4.y;
        As[kc + 2][lrow] = a4.z; As[kc + 3][lrow] = a4.w;

        float4 b4 = *(const float4*)(W + (size_t)(col0 + lrow) * HD + k0 + kc);
        Bs[kc + 0][lrow] = b4.x; Bs[kc + 1][lrow] = b4.y;
        Bs[kc + 2][lrow] = b4.z; Bs[kc + 3][lrow] = b4.w;
        __syncthreads();

#pragma unroll
        for (int kk = 0; kk < BK; kk++) {
            float4 av = *(const float4*)&As[kk][ty << 2];
            float4 bv2 = *(const float4*)&Bs[kk][tx << 2];
            float a[4] = {av.x, av.y, av.z, av.w};
            float b[4] = {bv2.x, bv2.y, bv2.z, bv2.w};
#pragma unroll
            for (int i = 0; i < 4; i++)
#pragma unroll
                for (int j = 0; j < 4; j++) acc[i][j] += a[i] * b[j];
        }
        __syncthreads();
    }

    const float LOG1E4_128 = 9.210340371976184f / 128.0f;
#pragma unroll
    for (int i = 0; i < 4; i++) {
        int s = lstart + (ty << 2) + i;        // spatial token index 0..1023
#pragma unroll
        for (int j = 0; j < 4; j++) {
            int o = col0 + (tx << 2) + j;
            float val = acc[i][j] + bias[o];
            if (pos) {
                int yg = s >> 5, xg = s & 31;
                int jj = o & 127;
                float omega = expf(-(float)jj * LOG1E4_128);
                float e;
                if (o < 128)      e = sinf((float)yg * omega);
                else if (o < 256) e = cosf((float)yg * omega);
                else if (o < 384) e = sinf((float)xg * omega);
                else              e = cosf((float)xg * omega);
                val += e;
            }
            dst[((size_t)bn * L + 1 + s) * HD + o] = val;
        }
    }
}

// ---------------------------------------------------------------------------
// Kernel 4: attention logits.  Per (b,n): C[1025,1025] = PQ * PK^T * scale.
// grid = (17, 17, 32)
// ---------------------------------------------------------------------------
__global__ __launch_bounds__(256) void k_logits()
{
    const int bn = blockIdx.z;
    const float* A = g_PQ + (size_t)bn * L * HD;
    const float* Bm = g_PK + (size_t)bn * L * HD;
    float* C = g_logits + (size_t)bn * L * L;

    __shared__ __align__(16) float As[BK][BM];
    __shared__ __align__(16) float Bs[BK][BN];

    const int tid = threadIdx.x;
    const int tx = tid & 15, ty = tid >> 4;
    const int row0 = blockIdx.y * BM;
    const int col0 = blockIdx.x * BN;
    const int lrow = tid >> 2;
    const int kc   = (tid & 3) << 2;

    float acc[4][4] = {};

    for (int k0 = 0; k0 < HD; k0 += BK) {
        float4 a4 = make_float4(0.f, 0.f, 0.f, 0.f);
        if (row0 + lrow < L) a4 = *(const float4*)(A + (size_t)(row0 + lrow) * HD + k0 + kc);
        As[kc + 0][lrow] = a4.x; As[kc + 1][lrow] = a4.y;
        As[kc + 2][lrow] = a4.z; As[kc + 3][lrow] = a4.w;

        float4 b4 = make_float4(0.f, 0.f, 0.f, 0.f);
        if (col0 + lrow < L) b4 = *(const float4*)(Bm + (size_t)(col0 + lrow) * HD + k0 + kc);
        Bs[kc + 0][lrow] = b4.x; Bs[kc + 1][lrow] = b4.y;
        Bs[kc + 2][lrow] = b4.z; Bs[kc + 3][lrow] = b4.w;
        __syncthreads();

#pragma unroll
        for (int kk = 0; kk < BK; kk++) {
            float4 av = *(const float4*)&As[kk][ty << 2];
            float4 bv2 = *(const float4*)&Bs[kk][tx << 2];
            float a[4] = {av.x, av.y, av.z, av.w};
            float b[4] = {bv2.x, bv2.y, bv2.z, bv2.w};
#pragma unroll
            for (int i = 0; i < 4; i++)
#pragma unroll
                for (int j = 0; j < 4; j++) acc[i][j] += a[i] * b[j];
        }
        __syncthreads();
    }

    const float scale = 0.044194173824159216f;   // 1/sqrt(512)
#pragma unroll
    for (int i = 0; i < 4; i++) {
        int q = row0 + (ty << 2) + i;
        if (q >= L) continue;
#pragma unroll
        for (int j = 0; j < 4; j++) {
            int k = col0 + (tx << 2) + j;
            if (k >= L) continue;
            C[(size_t)q * L + k] = acc[i][j] * scale;
        }
    }
}

// ---------------------------------------------------------------------------
// Kernel 5: rowwise softmax over 1025 keys, in place.  grid = 32800 rows.
// ---------------------------------------------------------------------------
__global__ __launch_bounds__(256) void k_softmax()
{
    float* p = g_logits + (size_t)blockIdx.x * L;
    __shared__ float red[256];
    const int tid = threadIdx.x;

    float m = -1e30f;
    for (int k = tid; k < L; k += 256) m = fmaxf(m, p[k]);
    red[tid] = m; __syncthreads();
    for (int s = 128; s > 0; s >>= 1) {
        if (tid < s) red[tid] = fmaxf(red[tid], red[tid + s]);
        __syncthreads();
    }
    m = red[0]; __syncthreads();

    float sum = 0.f;
    for (int k = tid; k < L; k += 256) {
        float e = expf(p[k] - m);
        p[k] = e;
        sum += e;
    }
    red[tid] = sum; __syncthreads();
    for (int s = 128; s > 0; s >>= 1) {
        if (tid < s) red[tid] += red[tid + s];
        __syncthreads();
    }
    float inv = 1.f / red[0];
    for (int k = tid; k < L; k += 256) p[k] *= inv;
}

// ---------------------------------------------------------------------------
// Kernel 6: AV GEMM + residual + restack.  Per (b,n):
// sa[1025,512] = attn[1025,1025] * PV[1025,512]; spatial rows += Q;
// write into stacked layout [b, l, n*512+c].  grid = (8, 17, 32)
// ---------------------------------------------------------------------------
__global__ __launch_bounds__(256) void k_av()
{
    const int bn = blockIdx.z;
    const float* A  = g_logits + (size_t)bn * L * L;   // [1025, 1025]
    const float* Bm = g_PV + (size_t)bn * L * HD;      // [1025, 512]

    __shared__ __align__(16) float As[BK][BM];
    __shared__ __align__(16) float Bs[BK][BN];

    const int tid = threadIdx.x;
    const int tx = tid & 15, ty = tid >> 4;
    const int row0 = blockIdx.y * BM;
    const int col0 = blockIdx.x * BN;

    float acc[4][4] = {};

    const int alrow = tid >> 2;           // A tile row 0..63
    const int akc   = (tid & 3) << 2;     // A tile k 0,4,8,12
    const int bkk   = tid >> 4;           // B tile k row 0..15
    const int bnc   = (tid & 15) << 2;    // B tile col 0..60

    for (int k0 = 0; k0 < L; k0 += BK) {
        int gr = row0 + alrow;
#pragma unroll
        for (int ii = 0; ii < 4; ii++) {
            int k = k0 + akc + ii;
            As[akc + ii][alrow] = (gr < L && k < L) ? A[(size_t)gr * L + k] : 0.f;
        }
        float4 b4 = make_float4(0.f, 0.f, 0.f, 0.f);
        if (k0 + bkk < L) b4 = *(const float4*)(Bm + (size_t)(k0 + bkk) * HD + col0 + bnc);
        *(float4*)&Bs[bkk][bnc] = b4;
        __syncthreads();

#pragma unroll
        for (int kk = 0; kk < BK; kk++) {
            float4 av = *(const float4*)&As[kk][ty << 2];
            float4 bv2 = *(const float4*)&Bs[kk][tx << 2];
            float a[4] = {av.x, av.y, av.z, av.w};
            float b[4] = {bv2.x, bv2.y, bv2.z, bv2.w};
#pragma unroll
            for (int i = 0; i < 4; i++)
#pragma unroll
                for (int j = 0; j < 4; j++) acc[i][j] += a[i] * b[j];
        }
        __syncthreads();
    }

    const int bb = bn >> 3, n = bn & 7;
#pragma unroll
    for (int i = 0; i < 4; i++) {
        int l = row0 + (ty << 2) + i;
        if (l >= L) continue;
#pragma unroll
        for (int j = 0; j < 4; j++) {
            int c = col0 + (tx << 2) + j;
            float val = acc[i][j];
            if (l > 0) val += g_Q[((size_t)bn * L + l) * HD + c];
            g_stacked[((size_t)(bb * L + l)) * QKVD + n * HD + c] = val;
        }
    }
}

// ---------------------------------------------------------------------------
// Kernel 7: output projection.  out[4100,512] = stacked[4100,4096] * Wd^T + bd
// grid = (8, 65)
// ---------------------------------------------------------------------------
__global__ __launch_bounds__(256) void k_out(
    const float* __restrict__ Wd, const float* __restrict__ bd,
    float* __restrict__ out)
{
    __shared__ __align__(16) float As[BK][BM];
    __shared__ __align__(16) float Bs[BK][BN];

    const int tid = threadIdx.x;
    const int tx = tid & 15, ty = tid >> 4;
    const int row0 = blockIdx.y * BM;
    const int col0 = blockIdx.x * BN;
    const int lrow = tid >> 2;
    const int kc   = (tid & 3) << 2;

    float acc[4][4] = {};

    for (int k0 = 0; k0 < QKVD; k0 += BK) {
        float4 a4 = make_float4(0.f, 0.f, 0.f, 0.f);
        int gr = row0 + lrow;
        if (gr < MQ) a4 = *(const float4*)(g_stacked + (size_t)gr * QKVD + k0 + kc);
        As[kc + 0][lrow] = a4.x; As[kc + 1][lrow] = a4.y;
        As[kc + 2][lrow] = a4.z; As[kc + 3][lrow] = a4.w;

        float4 b4 = *(const float4*)(Wd + (size_t)(col0 + lrow) * QKVD + k0 + kc);
        Bs[kc + 0][lrow] = b4.x; Bs[kc + 1][lrow] = b4.y;
        Bs[kc + 2][lrow] = b4.z; Bs[kc + 3][lrow] = b4.w;
        __syncthreads();

#pragma unroll
        for (int kk = 0; kk < BK; kk++) {
            float4 av = *(const float4*)&As[kk][ty << 2];
            float4 bv2 = *(const float4*)&Bs[kk][tx << 2];
            float a[4] = {av.x, av.y, av.z, av.w};
            float b[4] = {bv2.x, bv2.y, bv2.z, bv2.w};
#pragma unroll
            for (int i = 0; i < 4; i++)
#pragma unroll
                for (int j = 0; j < 4; j++) acc[i][j] += a[i] * b[j];
        }
        __syncthreads();
    }

#pragma unroll
    for (int i = 0; i < 4; i++) {
        int m = row0 + (ty << 2) + i;
        if (m >= MQ) continue;
#pragma unroll
        for (int j = 0; j < 4; j++) {
            int o = col0 + (tx << 2) + j;
            out[(size_t)m * IND + o] = acc[i][j] + bd[o];
        }
    }
}

// ---------------------------------------------------------------------------
// Launch
// ---------------------------------------------------------------------------
extern "C" void kernel_launch(void* const* d_in, const int* in_sizes, int n_in,
                              void* d_out, int out_size)
{
    const float* x   = (const float*)d_in[0];
    const float* Wq  = (const float*)d_in[1];
    const float* bq  = (const float*)d_in[2];
    const float* Wk  = (const float*)d_in[3];
    const float* bk  = (const float*)d_in[4];
    const float* Wv  = (const float*)d_in[5];
    const float* bv  = (const float*)d_in[6];
    const float* Wpq = (const float*)d_in[7];
    const float* bpq = (const float*)d_in[8];
    const float* Wpk = (const float*)d_in[9];
    const float* bpk = (const float*)d_in[10];
    const float* Wpv = (const float*)d_in[11];
    const float* bpv = (const float*)d_in[12];
    const float* Wd  = (const float*)d_in[13];
    const float* bd  = (const float*)d_in[14];
    float* out = (float*)d_out;

    dim3 t(256);
    k_qkv<<<dim3(QKVD / BN, (MQ + BM - 1) / BM, 3), t>>>(x, Wq, bq, Wk, bk, Wv, bv);
    k_cls<<<(3 * BH * HD + 255) / 256, 256>>>();
    k_pool<<<dim3(HD / BN, (BH * 1024) / BM, 3), t>>>(Wpq, bpq, Wpk, bpk, Wpv, bpv);
    k_logits<<<dim3((L + BN - 1) / BN, (L + BM - 1) / BM, BH), t>>>();
    k_softmax<<<BH * L, 256>>>();
    k_av<<<dim3(HD / BN, (L + BM - 1) / BM, BH), t>>>();
    k_out<<<dim3(IND / BN, (MQ + BM - 1) / BM), t>>>(Wd, bd, out);
}

// round 5
// speedup vs baseline: 1.2769x; 1.2769x over previous
#include <cuda_runtime.h>
#include <math.h>

#define BM 128
#define BN 128
#define BK 8
#define TS 136   // padded smem row stride

static constexpr int Bsz  = 4;
static constexpr int NH   = 8;
static constexpr int L    = 1025;
static constexpr int HD   = 512;
static constexpr int IND  = 512;
static constexpr int QKVD = 4096;
static constexpr int BH   = Bsz * NH;            // 32
static constexpr int MQ   = Bsz * L;             // 4100
static constexpr int LP   = 1028;                // padded logits row stride

static constexpr size_t QSZ  = (size_t)BH * L * HD;
static constexpr size_t LSZ  = (size_t)BH * L * LP;
static constexpr size_t SSZ  = (size_t)Bsz * L * QKVD;

__device__ float g_Q[QSZ];
__device__ float g_K[QSZ];
__device__ float g_V[QSZ];
__device__ float g_PQ[QSZ];
__device__ float g_PK[QSZ];
__device__ float g_PV[QSZ];
__device__ float g_logits[LSZ];    // zero-init; pad cols [1025,1028) never written
__device__ float g_stacked[SSZ];

// ---------------------------------------------------------------------------
// Shared helpers
// ---------------------------------------------------------------------------
__device__ __forceinline__ float4 f4zero() { return make_float4(0.f, 0.f, 0.f, 0.f); }

// store a float4 transposed into S[k][row] (for row-major [*,K] sources)
__device__ __forceinline__ void store_T(float (*S)[TS], int tid, float4 v) {
    int r = tid >> 1, c = (tid & 1) << 2;
    S[c + 0][r] = v.x; S[c + 1][r] = v.y; S[c + 2][r] = v.z; S[c + 3][r] = v.w;
}
// store a float4 directly into S[k][n] (for row-major [K,N] sources)
__device__ __forceinline__ void store_NN(float (*S)[TS], int tid, float4 v) {
    int k = tid >> 5, n = (tid & 31) << 2;
    *(float4*)&S[k][n] = v;
}

__device__ __forceinline__ void mm8x8(const float (*As_)[TS], const float (*Bs_)[TS],
                                      int tx, int ty, float acc[8][8]) {
#pragma unroll
    for (int kk = 0; kk < BK; kk++) {
        float4 a0 = *(const float4*)&As_[kk][ty << 2];
        float4 a1 = *(const float4*)&As_[kk][64 + (ty << 2)];
        float4 b0 = *(const float4*)&Bs_[kk][tx << 2];
        float4 b1 = *(const float4*)&Bs_[kk][64 + (tx << 2)];
        float a[8] = {a0.x, a0.y, a0.z, a0.w, a1.x, a1.y, a1.z, a1.w};
        float b[8] = {b0.x, b0.y, b0.z, b0.w, b1.x, b1.y, b1.z, b1.w};
#pragma unroll
        for (int i = 0; i < 8; i++)
#pragma unroll
            for (int j = 0; j < 8; j++) acc[i][j] += a[i] * b[j];
    }
}

#define EPI_IDX()                                                        \
    int rloc[8], cloc[8];                                                \
    _Pragma("unroll") for (int i = 0; i < 4; i++) {                      \
        rloc[i] = (ty << 2) + i;  rloc[i + 4] = 64 + (ty << 2) + i;      \
        cloc[i] = (tx << 2) + i;  cloc[i + 4] = 64 + (tx << 2) + i;      \
    }

// ---------------------------------------------------------------------------
// Kernel 1: QKV projection.  C[4100,4096] = x * W^T + b, scatter head-major.
// ---------------------------------------------------------------------------
__global__ __launch_bounds__(256, 2) void k_qkv(
    const float* __restrict__ x,
    const float* __restrict__ Wq, const float* __restrict__ bq,
    const float* __restrict__ Wk, const float* __restrict__ bk,
    const float* __restrict__ Wv, const float* __restrict__ bv)
{
    const float* W; const float* bias; float* out;
    if (blockIdx.z == 0)      { W = Wq; bias = bq; out = g_Q; }
    else if (blockIdx.z == 1) { W = Wk; bias = bk; out = g_K; }
    else                      { W = Wv; bias = bv; out = g_V; }

    __shared__ __align__(16) float As[2][BK][TS];
    __shared__ __align__(16) float Bs[2][BK][TS];

    const int tid = threadIdx.x, tx = tid & 15, ty = tid >> 4;
    const int row0 = blockIdx.y * BM, col0 = blockIdx.x * BN;
    const int ar = row0 + (tid >> 1), ac = (tid & 1) << 2;
    const bool av = ar < MQ;
    const float* Ap = x + (size_t)ar * IND + ac;
    const float* Bp = W + (size_t)(col0 + (tid >> 1)) * IND + ac;

    float acc[8][8] = {};
    store_T(As[0], tid, av ? *(const float4*)Ap : f4zero());
    store_T(Bs[0], tid, *(const float4*)Bp);
    __syncthreads();

    const int nt = IND / BK;
    for (int t = 0; t < nt; t++) {
        int cur = t & 1;
        float4 ra, rb;
        bool pf = (t + 1 < nt);
        const float* Apn = Ap + (t + 1) * BK;
        const float* Bpn = Bp + (t + 1) * BK;
        if (pf) {
            ra = av ? *(const float4*)Apn : f4zero();
            rb = *(const float4*)Bpn;
        }
        mm8x8(As[cur], Bs[cur], tx, ty, acc);
        if (pf) { store_T(As[cur ^ 1], tid, ra); store_T(Bs[cur ^ 1], tid, rb); }
        __syncthreads();
    }

    EPI_IDX();
#pragma unroll
    for (int i = 0; i < 8; i++) {
        int m = row0 + rloc[i];
        if (m >= MQ) continue;
        int bb = m / L, l = m % L;
#pragma unroll
        for (int j = 0; j < 8; j++) {
            int o = col0 + cloc[j];
            int n = o >> 9, c = o & 511;
            out[(((size_t)(bb * NH + n)) * L + l) * HD + c] = acc[i][j] + bias[o];
        }
    }
}

// ---------------------------------------------------------------------------
// Kernel 2: copy cls tokens through the pooler unchanged.
// ---------------------------------------------------------------------------
__global__ __launch_bounds__(256) void k_cls()
{
    int idx = blockIdx.x * blockDim.x + threadIdx.x;
    if (idx >= 3 * BH * HD) return;
    int t = idx / (BH * HD), rem = idx % (BH * HD);
    int bn = rem / HD, c = rem % HD;
    size_t off = (size_t)bn * L * HD + c;
    if (t == 0)      g_PQ[off] = g_Q[off];
    else if (t == 1) g_PK[off] = g_K[off];
    else             g_PV[off] = g_V[off];
}

// ---------------------------------------------------------------------------
// Kernel 3: pooler GEMM on spatial tokens + bias (+ pos-embed for PQ).
// grid = (4, 256, 3): y = bn*8 + row-tile
// ---------------------------------------------------------------------------
__global__ __launch_bounds__(256, 2) void k_pool(
    const float* __restrict__ Wpq, const float* __restrict__ bpq,
    const float* __restrict__ Wpk, const float* __restrict__ bpk,
    const float* __restrict__ Wpv, const float* __restrict__ bpv)
{
    const float* src; const float* W; const float* bias; float* dst; bool pos;
    if (blockIdx.z == 0)      { src = g_Q; W = Wpq; bias = bpq; dst = g_PQ; pos = true; }
    else if (blockIdx.z == 1) { src = g_K; W = Wpk; bias = bpk; dst = g_PK; pos = false; }
    else                      { src = g_V; W = Wpv; bias = bpv; dst = g_PV; pos = false; }

    const int bn = blockIdx.y >> 3;
    const int lstart = (blockIdx.y & 7) * BM;
    const float* A = src + ((size_t)bn * L + 1 + lstart) * HD;

    __shared__ __align__(16) float As[2][BK][TS];
    __shared__ __align__(16) float Bs[2][BK][TS];

    const int tid = threadIdx.x, tx = tid & 15, ty = tid >> 4;
    const int col0 = blockIdx.x * BN;
    const int ac = (tid & 1) << 2;
    const float* Ap = A + (size_t)(tid >> 1) * HD + ac;
    const float* Bp = W + (size_t)(col0 + (tid >> 1)) * HD + ac;

    float acc[8][8] = {};
    store_T(As[0], tid, *(const float4*)Ap);
    store_T(Bs[0], tid, *(const float4*)Bp);
    __syncthreads();

    const int nt = HD / BK;
    for (int t = 0; t < nt; t++) {
        int cur = t & 1;
        float4 ra, rb;
        bool pf = (t + 1 < nt);
        const float* Apn = Ap + (t + 1) * BK;
        const float* Bpn = Bp + (t + 1) * BK;
        if (pf) {
            ra = *(const float4*)Apn;
            rb = *(const float4*)Bpn;
        }
        mm8x8(As[cur], Bs[cur], tx, ty, acc);
        if (pf) { store_T(As[cur ^ 1], tid, ra); store_T(Bs[cur ^ 1], tid, rb); }
        __syncthreads();
    }

    EPI_IDX();
    const float LOG1E4_128 = 9.210340371976184f / 128.0f;
#pragma unroll
    for (int i = 0; i < 8; i++) {
        int s = lstart + rloc[i];
#pragma unroll
        for (int j = 0; j < 8; j++) {
            int o = col0 + cloc[j];
            float val = acc[i][j] + bias[o];
            if (pos) {
                int yg = s >> 5, xg = s & 31;
                float omega = expf(-(float)(o & 127) * LOG1E4_128);
                float e;
                if (o < 128)      e = sinf((float)yg * omega);
                else if (o < 256) e = cosf((float)yg * omega);
                else if (o < 384) e = sinf((float)xg * omega);
                else              e = cosf((float)xg * omega);
                val += e;
            }
            dst[((size_t)bn * L + 1 + s) * HD + o] = val;
        }
    }
}

// ---------------------------------------------------------------------------
// Kernel 4: logits = PQ * PK^T * scale.  grid = (9, 9, 32)
// ---------------------------------------------------------------------------
__global__ __launch_bounds__(256, 2) void k_logits()
{
    const int bn = blockIdx.z;
    const float* A  = g_PQ + (size_t)bn * L * HD;
    const float* Bm = g_PK + (size_t)bn * L * HD;
    float* C = g_logits + (size_t)bn * L * LP;

    __shared__ __align__(16) float As[2][BK][TS];
    __shared__ __align__(16) float Bs[2][BK][TS];

    const int tid = threadIdx.x, tx = tid & 15, ty = tid >> 4;
    const int row0 = blockIdx.y * BM, col0 = blockIdx.x * BN;
    const int ar = row0 + (tid >> 1), br = col0 + (tid >> 1), ac = (tid & 1) << 2;
    const bool avld = ar < L, bvld = br < L;
    const float* Ap = A + (size_t)ar * HD + ac;
    const float* Bp = Bm + (size_t)br * HD + ac;

    float acc[8][8] = {};
    store_T(As[0], tid, avld ? *(const float4*)Ap : f4zero());
    store_T(Bs[0], tid, bvld ? *(const float4*)Bp : f4zero());
    __syncthreads();

    const int nt = HD / BK;
    for (int t = 0; t < nt; t++) {
        int cur = t & 1;
        float4 ra, rb;
        bool pf = (t + 1 < nt);
        const float* Apn = Ap + (t + 1) * BK;
        const float* Bpn = Bp + (t + 1) * BK;
        if (pf) {
            ra = avld ? *(const float4*)Apn : f4zero();
            rb = bvld ? *(const float4*)Bpn : f4zero();
        }
        mm8x8(As[cur], Bs[cur], tx, ty, acc);
        if (pf) { store_T(As[cur ^ 1], tid, ra); store_T(Bs[cur ^ 1], tid, rb); }
        __syncthreads();
    }

    EPI_IDX();
    const float scale = 0.044194173824159216f;   // 1/sqrt(512)
#pragma unroll
    for (int i = 0; i < 8; i++) {
        int q = row0 + rloc[i];
        if (q >= L) continue;
#pragma unroll
        for (int j = 0; j < 8; j++) {
            int k = col0 + cloc[j];
            if (k < L) C[(size_t)q * LP + k] = acc[i][j] * scale;
        }
    }
}

// ---------------------------------------------------------------------------
// Kernel 5: rowwise softmax, values register-cached (1 read + 1 write).
// ---------------------------------------------------------------------------
__global__ __launch_bounds__(256) void k_softmax()
{
    float* p = g_logits + (size_t)blockIdx.x * LP;
    __shared__ float red[256];
    const int tid = threadIdx.x;

    float v[5];
#pragma unroll
    for (int i = 0; i < 4; i++) v[i] = p[tid + (i << 8)];
    v[4] = (tid == 0) ? p[1024] : -1e30f;

    float m = v[0];
#pragma unroll
    for (int i = 1; i < 5; i++) m = fmaxf(m, v[i]);
    red[tid] = m; __syncthreads();
    for (int s = 128; s > 0; s >>= 1) {
        if (tid < s) red[tid] = fmaxf(red[tid], red[tid + s]);
        __syncthreads();
    }
    m = red[0]; __syncthreads();

    float sum = 0.f;
#pragma unroll
    for (int i = 0; i < 5; i++) { v[i] = expf(v[i] - m); sum += v[i]; }
    red[tid] = sum; __syncthreads();
    for (int s = 128; s > 0; s >>= 1) {
        if (tid < s) red[tid] += red[tid + s];
        __syncthreads();
    }
    float inv = 1.f / red[0];
#pragma unroll
    for (int i = 0; i < 4; i++) p[tid + (i << 8)] = v[i] * inv;
    if (tid == 0) p[1024] = v[4] * inv;
}

// ---------------------------------------------------------------------------
// Kernel 6: sa = attn * PV (+residual, restack).  grid = (4, 9, 32)
// A is [L, LP] (K=1025, padded cols are zero), B is [L, HD] row-major (NN).
// ---------------------------------------------------------------------------
__global__ __launch_bounds__(256, 2) void k_av()
{
    const int bn = blockIdx.z;
    const float* A  = g_logits + (size_t)bn * L * LP;
    const float* Bm = g_PV + (size_t)bn * L * HD;

    __shared__ __align__(16) float As[2][BK][TS];
    __shared__ __align__(16) float Bs[2][BK][TS];

    const int tid = threadIdx.x, tx = tid & 15, ty = tid >> 4;
    const int row0 = blockIdx.y * BM, col0 = blockIdx.x * BN;
    const int ar = row0 + (tid >> 1), ac = (tid & 1) << 2;
    const bool avld = ar < L;
    const float* Ap = A + (size_t)ar * LP + ac;
    const int bk = tid >> 5, bn4 = (tid & 31) << 2;
    const float* Bp = Bm + (size_t)bk * HD + col0 + bn4;

    float acc[8][8] = {};
    store_T(As[0], tid, avld ? *(const float4*)Ap : f4zero());
    store_NN(Bs[0], tid, *(const float4*)Bp);   // bk < 8 < L always valid at t=0
    __syncthreads();

    const int nt = (L + BK - 1) / BK;           // 129
    for (int t = 0; t < nt; t++) {
        int cur = t & 1;
        float4 ra, rb;
        bool pf = (t + 1 < nt);
        int k0 = (t + 1) * BK;
        if (pf) {
            ra = (avld && (k0 + ac) < LP) ? *(const float4*)(Ap + k0) : f4zero();
            rb = ((k0 + bk) < L) ? *(const float4*)(Bp + (size_t)k0 * HD) : f4zero();
        }
        mm8x8(As[cur], Bs[cur], tx, ty, acc);
        if (pf) { store_T(As[cur ^ 1], tid, ra); store_NN(Bs[cur ^ 1], tid, rb); }
        __syncthreads();
    }

    EPI_IDX();
    const int bb = bn >> 3, n = bn & 7;
#pragma unroll
    for (int i = 0; i < 8; i++) {
        int l = row0 + rloc[i];
        if (l >= L) continue;
#pragma unroll
        for (int j = 0; j < 8; j++) {
            int c = col0 + cloc[j];
            float val = acc[i][j];
            if (l > 0) val += g_Q[((size_t)bn * L + l) * HD + c];
            g_stacked[((size_t)(bb * L + l)) * QKVD + n * HD + c] = val;
        }
    }
}

// ---------------------------------------------------------------------------
// Kernel 7: out = stacked * Wd^T + bd.  grid = (4, 33)
// ---------------------------------------------------------------------------
__global__ __launch_bounds__(256, 2) void k_out(
    const float* __restrict__ Wd, const float* __restrict__ bd,
    float* __restrict__ out)
{
    __shared__ __align__(16) float As[2][BK][TS];
    __shared__ __align__(16) float Bs[2][BK][TS];

    const int tid = threadIdx.x, tx = tid & 15, ty = tid >> 4;
    const int row0 = blockIdx.y * BM, col0 = blockIdx.x * BN;
    const int ar = row0 + (tid >> 1), ac = (tid & 1) << 2;
    const bool avld = ar < MQ;
    const float* Ap = g_stacked + (size_t)ar * QKVD + ac;
    const float* Bp = Wd + (size_t)(col0 + (tid >> 1)) * QKVD + ac;

    float acc[8][8] = {};
    store_T(As[0], tid, avld ? *(const float4*)Ap : f4zero());
    store_T(Bs[0], tid, *(const float4*)Bp);
    __syncthreads();

    const int nt = QKVD / BK;
    for (int t = 0; t < nt; t++) {
        int cur = t & 1;
        float4 ra, rb;
        bool pf = (t + 1 < nt);
        const float* Apn = Ap + (t + 1) * BK;
        const float* Bpn = Bp + (t + 1) * BK;
        if (pf) {
            ra = avld ? *(const float4*)Apn : f4zero();
            rb = *(const float4*)Bpn;
        }
        mm8x8(As[cur], Bs[cur], tx, ty, acc);
        if (pf) { store_T(As[cur ^ 1], tid, ra); store_T(Bs[cur ^ 1], tid, rb); }
        __syncthreads();
    }

    EPI_IDX();
#pragma unroll
    for (int i = 0; i < 8; i++) {
        int m = row0 + rloc[i];
        if (m >= MQ) continue;
#pragma unroll
        for (int j = 0; j < 8; j++) {
            int o = col0 + cloc[j];
            out[(size_t)m * IND + o] = acc[i][j] + bd[o];
        }
    }
}

// ---------------------------------------------------------------------------
// Launch
// ---------------------------------------------------------------------------
extern "C" void kernel_launch(void* const* d_in, const int* in_sizes, int n_in,
                              void* d_out, int out_size)
{
    const float* x   = (const float*)d_in[0];
    const float* Wq  = (const float*)d_in[1];
    const float* bq  = (const float*)d_in[2];
    const float* Wk  = (const float*)d_in[3];
    const float* bk  = (const float*)d_in[4];
    const float* Wv  = (const float*)d_in[5];
    const float* bv  = (const float*)d_in[6];
    const float* Wpq = (const float*)d_in[7];
    const float* bpq = (const float*)d_in[8];
    const float* Wpk = (const float*)d_in[9];
    const float* bpk = (const float*)d_in[10];
    const float* Wpv = (const float*)d_in[11];
    const float* bpv = (const float*)d_in[12];
    const float* Wd  = (const float*)d_in[13];
    const float* bd  = (const float*)d_in[14];
    float* out = (float*)d_out;

    dim3 t(256);
    k_qkv<<<dim3(QKVD / BN, (MQ + BM - 1) / BM, 3), t>>>(x, Wq, bq, Wk, bk, Wv, bv);
    k_cls<<<(3 * BH * HD + 255) / 256, 256>>>();
    k_pool<<<dim3(HD / BN, BH * (1024 / BM), 3), t>>>(Wpq, bpq, Wpk, bpk, Wpv, bpv);
    k_logits<<<dim3((L + BN - 1) / BN, (L + BM - 1) / BM, BH), t>>>();
    k_softmax<<<BH * L, 256>>>();
    k_av<<<dim3(HD / BN, (L + BM - 1) / BM, BH), t>>>();
    k_out<<<dim3(IND / BN, (MQ + BM - 1) / BM), t>>>(Wd, bd, out);
}

// round 7
// speedup vs baseline: 2.5061x; 1.9627x over previous
#include <cuda_runtime.h>
#include <cuda_bf16.h>
#include <cstdint>
#include <math.h>

// ============================================================================
// Problem constants
// ============================================================================
static constexpr int Bsz  = 4;
static constexpr int NH   = 8;
static constexpr int L    = 1025;
static constexpr int HD   = 512;
static constexpr int IND  = 512;
static constexpr int QKVD = 4096;
static constexpr int BH   = Bsz * NH;          // 32
static constexpr int MQ   = Bsz * L;           // 4100
static constexpr int MP   = 4224;              // padded M rows (33*128)
static constexpr int LR   = 1152;              // padded rows per (b,n) (9*128)
static constexpr int KA   = 1088;              // padded attn K cols (17*64)
static constexpr int LP   = 1028;              // fp32 logits row stride

// ============================================================================
// Global scratch (zero-initialized; pad regions never written)
// ============================================================================
__device__ __align__(16) __nv_bfloat16 g_xh[MP * IND];
__device__ __align__(16) __nv_bfloat16 g_xl[MP * IND];
__device__ __align__(16) __nv_bfloat16 g_Wh[3][QKVD * IND];
__device__ __align__(16) __nv_bfloat16 g_Wl[3][QKVD * IND];
__device__ __align__(16) __nv_bfloat16 g_Wph[3][HD * HD];
__device__ __align__(16) __nv_bfloat16 g_Wpl[3][HD * HD];
__device__ __align__(16) __nv_bfloat16 g_Wdh[IND * QKVD];
__device__ __align__(16) __nv_bfloat16 g_Wdl[IND * QKVD];
__device__ __align__(16) __nv_bfloat16 g_QKVh[3][(size_t)BH * L * HD];
__device__ __align__(16) __nv_bfloat16 g_QKVl[3][(size_t)BH * L * HD];
__device__ __align__(16) __nv_bfloat16 g_Ph[2][(size_t)BH * LR * HD];    // PQ, PK (token-major)
__device__ __align__(16) __nv_bfloat16 g_Pl[2][(size_t)BH * LR * HD];
__device__ __align__(16) __nv_bfloat16 g_PVth[(size_t)BH * HD * LR];     // PV transposed [hd][token]
__device__ __align__(16) __nv_bfloat16 g_PVtl[(size_t)BH * HD * LR];
__device__ __align__(16) float         g_logits[(size_t)BH * L * LP];
__device__ __align__(16) __nv_bfloat16 g_ah[(size_t)BH * LR * KA];
__device__ __align__(16) __nv_bfloat16 g_al[(size_t)BH * LR * KA];
__device__ __align__(16) __nv_bfloat16 g_sh[(size_t)MP * QKVD];
__device__ __align__(16) __nv_bfloat16 g_sl[(size_t)MP * QKVD];

// ============================================================================
// HMMA GEMM core: 128x128 CTA tile, 8 warps of 64x32, k-chunks of 64.
// smem: 4 tiles [128][AS] bf16 (Ahi, Alo, Bhi, Blo), AS=72 (144B rows).
// ============================================================================
#define AS 72
#define KC 64
static constexpr size_t SMEM_BYTES = (size_t)4 * 128 * AS * sizeof(__nv_bfloat16); // 73728

__device__ __forceinline__ void mma_bf16(float* d,
    uint32_t a0, uint32_t a1, uint32_t a2, uint32_t a3, uint32_t b0, uint32_t b1)
{
    asm volatile(
        "mma.sync.aligned.m16n8k16.row.col.f32.bf16.bf16.f32 "
        "{%0,%1,%2,%3}, {%4,%5,%6,%7}, {%8,%9}, {%0,%1,%2,%3};"
        : "+f"(d[0]), "+f"(d[1]), "+f"(d[2]), "+f"(d[3])
        : "r"(a0), "r"(a1), "r"(a2), "r"(a3), "r"(b0), "r"(b1));
}

__device__ __forceinline__ void ldg_tile(__nv_bfloat16* dst,
    const __nv_bfloat16* __restrict__ src, size_t stride, int tid)
{
#pragma unroll
    for (int j = 0; j < 4; j++) {
        int ci = tid + j * 256;          // 0..1023
        int r = ci >> 3, c = (ci & 7) * 8;
        uint4 v = *(const uint4*)(src + (size_t)r * stride + c);
        *(uint4*)(dst + r * AS + c) = v;
    }
}

// Fills acc[4][4][4]. A: [128 rows, K] K-major hi/lo. B: [128 n-rows, K] K-major hi/lo.
__device__ __forceinline__ void gemm_core(char* smem,
    const __nv_bfloat16* Ah, const __nv_bfloat16* Al, size_t sA,
    const __nv_bfloat16* Bh, const __nv_bfloat16* Bl, size_t sB,
    int kt, float acc[4][4][4])
{
    __nv_bfloat16* sAh = (__nv_bfloat16*)smem;
    __nv_bfloat16* sAl = sAh + 128 * AS;
    __nv_bfloat16* sBh = sAl + 128 * AS;
    __nv_bfloat16* sBl = sBh + 128 * AS;
    const int tid = threadIdx.x, lane = tid & 31, wid = tid >> 5;
    const int wm = wid >> 2, wn = wid & 3;
    const int rbase = wm * 64 + (lane >> 2);
    const int nbase = wn * 32 + (lane >> 2);
    const int kb = (lane & 3) * 2;

    for (int t = 0; t < kt; t++) {
        if (t) __syncthreads();
        ldg_tile(sAh, Ah + t * KC, sA, tid);
        ldg_tile(sAl, Al + t * KC, sA, tid);
        ldg_tile(sBh, Bh + t * KC, sB, tid);
        ldg_tile(sBl, Bl + t * KC, sB, tid);
        __syncthreads();
#pragma unroll
        for (int kk = 0; kk < 4; kk++) {
            const int k0 = kk * 16 + kb;
            uint32_t bhf[4][2], blf[4][2];
#pragma unroll
            for (int j = 0; j < 4; j++) {
                int n = nbase + j * 8;
                bhf[j][0] = *(const uint32_t*)(sBh + n * AS + k0);
                bhf[j][1] = *(const uint32_t*)(sBh + n * AS + k0 + 8);
                blf[j][0] = *(const uint32_t*)(sBl + n * AS + k0);
                blf[j][1] = *(const uint32_t*)(sBl + n * AS + k0 + 8);
            }
#pragma unroll
            for (int i = 0; i < 4; i++) {
                int r = rbase + i * 16;
                uint32_t ah0 = *(const uint32_t*)(sAh + r * AS + k0);
                uint32_t ah1 = *(const uint32_t*)(sAh + (r + 8) * AS + k0);
                uint32_t ah2 = *(const uint32_t*)(sAh + r * AS + k0 + 8);
                uint32_t ah3 = *(const uint32_t*)(sAh + (r + 8) * AS + k0 + 8);
                uint32_t al0 = *(const uint32_t*)(sAl + r * AS + k0);
                uint32_t al1 = *(const uint32_t*)(sAl + (r + 8) * AS + k0);
                uint32_t al2 = *(const uint32_t*)(sAl + r * AS + k0 + 8);
                uint32_t al3 = *(const uint32_t*)(sAl + (r + 8) * AS + k0 + 8);
#pragma unroll
                for (int j = 0; j < 4; j++) {
                    mma_bf16(acc[i][j], ah0, ah1, ah2, ah3, bhf[j][0], bhf[j][1]);
                    mma_bf16(acc[i][j], ah0, ah1, ah2, ah3, blf[j][0], blf[j][1]);
                    mma_bf16(acc[i][j], al0, al1, al2, al3, bhf[j][0], bhf[j][1]);
                }
            }
        }
    }
}

__device__ __forceinline__ void split_bf(float v, __nv_bfloat16* hp, __nv_bfloat16* lp) {
    __nv_bfloat16 h = __float2bfloat16(v);
    *hp = h;
    *lp = __float2bfloat16(v - __bfloat162float(h));
}

// epilogue element coordinates: p in 0..3 -> (row + (p>>1)*8, col + (p&1))
#define EPI_SETUP() \
    const int lane = threadIdx.x & 31, wid_ = threadIdx.x >> 5; \
    const int wm = wid_ >> 2, wn = wid_ & 3; \
    const int er0 = wm * 64 + (lane >> 2); \
    const int ec0 = wn * 32 + (lane & 3) * 2;

// ============================================================================
// Conversion: fp32 -> bf16 hi/lo
// ============================================================================
__global__ __launch_bounds__(256) void k_conv(const float* __restrict__ src,
    __nv_bfloat16* __restrict__ hi, __nv_bfloat16* __restrict__ lo, int n)
{
    int i = blockIdx.x * 256 + threadIdx.x;
    if (i < n) {
        float v = src[i];
        __nv_bfloat16 h = __float2bfloat16(v);
        hi[i] = h;
        lo[i] = __float2bfloat16(v - __bfloat162float(h));
    }
}

// ============================================================================
// QKV projection.  grid (32, 33, 3)
// ============================================================================
__global__ __launch_bounds__(256, 2) void k_qkv_mma(
    const float* __restrict__ bq, const float* __restrict__ bk, const float* __restrict__ bv)
{
    extern __shared__ char smem[];
    const int z = blockIdx.z;
    const int row0 = blockIdx.y * 128, col0 = blockIdx.x * 128;
    const float* bias = (z == 0) ? bq : (z == 1) ? bk : bv;

    float acc[4][4][4] = {};
    gemm_core(smem,
        g_xh + (size_t)row0 * IND, g_xl + (size_t)row0 * IND, IND,
        g_Wh[z] + (size_t)col0 * IND, g_Wl[z] + (size_t)col0 * IND, IND,
        IND / KC, acc);

    EPI_SETUP();
    __nv_bfloat16* oh = g_QKVh[z];
    __nv_bfloat16* ol = g_QKVl[z];
#pragma unroll
    for (int i = 0; i < 4; i++)
#pragma unroll
        for (int p2 = 0; p2 < 2; p2++) {
            int m = row0 + er0 + i * 16 + p2 * 8;
            if (m >= MQ) continue;
            int bb = m / L, l = m - bb * L;
#pragma unroll
            for (int j = 0; j < 4; j++)
#pragma unroll
                for (int p1 = 0; p1 < 2; p1++) {
                    int o = col0 + ec0 + j * 8 + p1;
                    int n = o >> 9, ch = o & 511;
                    float v = acc[i][j][p2 * 2 + p1] + bias[o];
                    size_t idx = (((size_t)(bb * NH + n)) * L + l) * HD + ch;
                    split_bf(v, &oh[idx], &ol[idx]);
                }
        }
}

// ============================================================================
// cls passthrough
// ============================================================================
__global__ __launch_bounds__(256) void k_cls2()
{
    int idx = blockIdx.x * 256 + threadIdx.x;
    if (idx >= 3 * BH * HD) return;
    int z = idx / (BH * HD), rem = idx % (BH * HD);
    int bn = rem / HD, c = rem % HD;
    size_t so = ((size_t)bn * L) * HD + c;
    if (z < 2) {
        size_t d = ((size_t)bn * LR) * HD + c;
        g_Ph[z][d] = g_QKVh[z][so];
        g_Pl[z][d] = g_QKVl[z][so];
    } else {
        size_t d = ((size_t)bn * HD + c) * LR;   // token 0
        g_PVth[d] = g_QKVh[2][so];
        g_PVtl[d] = g_QKVl[2][so];
    }
}

// ============================================================================
// Pooler GEMM.  grid (4, 256, 3); y = bn*8 + mt.  z==2 writes PV transposed.
// ============================================================================
__global__ __launch_bounds__(256, 2) void k_pool_mma(
    const float* __restrict__ bpq, const float* __restrict__ bpk, const float* __restrict__ bpv)
{
    extern __shared__ char smem[];
    const int z = blockIdx.z;
    const int bn = blockIdx.y >> 3, mt = blockIdx.y & 7;
    const int col0 = blockIdx.x * 128;
    const float* bias = (z == 0) ? bpq : (z == 1) ? bpk : bpv;

    size_t arow = ((size_t)bn * L + 1 + mt * 128) * HD;
    float acc[4][4][4] = {};
    gemm_core(smem,
        g_QKVh[z] + arow, g_QKVl[z] + arow, HD,
        g_Wph[z] + (size_t)col0 * HD, g_Wpl[z] + (size_t)col0 * HD, HD,
        HD / KC, acc);

    EPI_SETUP();
    const float LOG1E4_128 = 9.210340371976184f / 128.0f;
#pragma unroll
    for (int i = 0; i < 4; i++)
#pragma unroll
        for (int p2 = 0; p2 < 2; p2++) {
            int s = mt * 128 + er0 + i * 16 + p2 * 8;     // spatial token 0..1023
#pragma unroll
            for (int j = 0; j < 4; j++)
#pragma unroll
                for (int p1 = 0; p1 < 2; p1++) {
                    int o = col0 + ec0 + j * 8 + p1;
                    float v = acc[i][j][p2 * 2 + p1] + bias[o];
                    if (z == 0) {
                        int yg = s >> 5, xg = s & 31;
                        float omega = expf(-(float)(o & 127) * LOG1E4_128);
                        float e;
                        if (o < 128)      e = sinf((float)yg * omega);
                        else if (o < 256) e = cosf((float)yg * omega);
                        else if (o < 384) e = sinf((float)xg * omega);
                        else              e = cosf((float)xg * omega);
                        v += e;
                    }
                    if (z < 2) {
                        size_t idx = ((size_t)bn * LR + 1 + s) * HD + o;
                        split_bf(v, &g_Ph[z][idx], &g_Pl[z][idx]);
                    } else {
                        size_t idx = ((size_t)bn * HD + o) * LR + 1 + s;
                        split_bf(v, &g_PVth[idx], &g_PVtl[idx]);
                    }
                }
        }
}

// ============================================================================
// Logits = PQ * PK^T * scale.  grid (9, 9, 32)
// ============================================================================
__global__ __launch_bounds__(256, 2) void k_logits_mma()
{
    extern __shared__ char smem[];
    const int bn = blockIdx.z;
    const int row0 = blockIdx.y * 128, col0 = blockIdx.x * 128;

    size_t abase = ((size_t)bn * LR + row0) * HD;
    size_t bbase = ((size_t)bn * LR + col0) * HD;
    float acc[4][4][4] = {};
    gemm_core(smem,
        g_Ph[0] + abase, g_Pl[0] + abase, HD,
        g_Ph[1] + bbase, g_Pl[1] + bbase, HD,
        HD / KC, acc);

    EPI_SETUP();
    const float scale = 0.044194173824159216f;   // 1/sqrt(512)
    float* dstb = g_logits + (size_t)bn * L * LP;
#pragma unroll
    for (int i = 0; i < 4; i++)
#pragma unroll
        for (int p2 = 0; p2 < 2; p2++) {
            int q = row0 + er0 + i * 16 + p2 * 8;
            if (q >= L) continue;
            float* dst = dstb + (size_t)q * LP;
#pragma unroll
            for (int j = 0; j < 4; j++)
#pragma unroll
                for (int p1 = 0; p1 < 2; p1++) {
                    int k = col0 + ec0 + j * 8 + p1;
                    if (k < L) dst[k] = acc[i][j][p2 * 2 + p1] * scale;
                }
        }
}

// ============================================================================
// Softmax -> attn hi/lo bf16.  grid (1025, 32)
// ============================================================================
__global__ __launch_bounds__(256) void k_softmax_mma()
{
    const int bn = blockIdx.y, row = blockIdx.x;
    const float* p = g_logits + ((size_t)bn * L + row) * LP;
    __nv_bfloat16* oh = g_ah + ((size_t)bn * LR + row) * KA;
    __nv_bfloat16* ol = g_al + ((size_t)bn * LR + row) * KA;
    __shared__ float red[256];
    const int tid = threadIdx.x;

    float v[5];
#pragma unroll
    for (int i = 0; i < 4; i++) v[i] = p[tid + (i << 8)];
    v[4] = (tid == 0) ? p[1024] : -1e30f;

    float m = v[0];
#pragma unroll
    for (int i = 1; i < 5; i++) m = fmaxf(m, v[i]);
    red[tid] = m; __syncthreads();
    for (int s = 128; s > 0; s >>= 1) {
        if (tid < s) red[tid] = fmaxf(red[tid], red[tid + s]);
        __syncthreads();
    }
    m = red[0]; __syncthreads();

    float sum = 0.f;
#pragma unroll
    for (int i = 0; i < 5; i++) { v[i] = expf(v[i] - m); sum += v[i]; }
    red[tid] = sum; __syncthreads();
    for (int s = 128; s > 0; s >>= 1) {
        if (tid < s) red[tid] += red[tid + s];
        __syncthreads();
    }
    float inv = 1.f / red[0];

#pragma unroll
    for (int i = 0; i < 4; i++) {
        int k = tid + (i << 8);
        split_bf(v[i] * inv, &oh[k], &ol[k]);
    }
    if (tid == 0) split_bf(v[4] * inv, &oh[1024], &ol[1024]);
}

// ============================================================================
// AV GEMM + residual + restack.  grid (4, 9, 32)
// A = attn [row][k] (stride KA), B = PVt [hd][token] (stride LR)
// ============================================================================
__global__ __launch_bounds__(256, 2) void k_av_mma()
{
    extern __shared__ char smem[];
    const int bn = blockIdx.z;
    const int row0 = blockIdx.y * 128, col0 = blockIdx.x * 128;

    float acc[4][4][4] = {};
    gemm_core(smem,
        g_ah + ((size_t)bn * LR + row0) * KA, g_al + ((size_t)bn * LR + row0) * KA, KA,
        g_PVth + ((size_t)bn * HD + col0) * LR, g_PVtl + ((size_t)bn * HD + col0) * LR, LR,
        KA / KC, acc);

    EPI_SETUP();
    const int bb = bn >> 3, n = bn & 7;
#pragma unroll
    for (int i = 0; i < 4; i++)
#pragma unroll
        for (int p2 = 0; p2 < 2; p2++) {
            int l = row0 + er0 + i * 16 + p2 * 8;
            if (l >= L) continue;
            size_t qb = ((size_t)bn * L + l) * HD;
            size_t sb = ((size_t)(bb * L + l)) * QKVD + n * HD;
#pragma unroll
            for (int j = 0; j < 4; j++)
#pragma unroll
                for (int p1 = 0; p1 < 2; p1++) {
                    int c = col0 + ec0 + j * 8 + p1;
                    float v = acc[i][j][p2 * 2 + p1];
                    if (l > 0)
                        v += __bfloat162float(g_QKVh[0][qb + c]) + __bfloat162float(g_QKVl[0][qb + c]);
                    split_bf(v, &g_sh[sb + c], &g_sl[sb + c]);
                }
        }
}

// ============================================================================
// Output projection.  grid (4, 33)
// ============================================================================
__global__ __launch_bounds__(256, 2) void k_out_mma(
    const float* __restrict__ bd, float* __restrict__ out)
{
    extern __shared__ char smem[];
    const int row0 = blockIdx.y * 128, col0 = blockIdx.x * 128;

    float acc[4][4][4] = {};
    gemm_core(smem,
        g_sh + (size_t)row0 * QKVD, g_sl + (size_t)row0 * QKVD, QKVD,
        g_Wdh + (size_t)col0 * QKVD, g_Wdl + (size_t)col0 * QKVD, QKVD,
        QKVD / KC, acc);

    EPI_SETUP();
#pragma unroll
    for (int i = 0; i < 4; i++)
#pragma unroll
        for (int p2 = 0; p2 < 2; p2++) {
            int m = row0 + er0 + i * 16 + p2 * 8;
            if (m >= MQ) continue;
            float* dst = out + (size_t)m * IND;
#pragma unroll
            for (int j = 0; j < 4; j++)
#pragma unroll
                for (int p1 = 0; p1 < 2; p1++) {
                    int o = col0 + ec0 + j * 8 + p1;
                    dst[o] = acc[i][j][p2 * 2 + p1] + bd[o];
                }
        }
}

// ============================================================================
// Launch
// ============================================================================
extern "C" void kernel_launch(void* const* d_in, const int* in_sizes, int n_in,
                              void* d_out, int out_size)
{
    const float* x   = (const float*)d_in[0];
    const float* Wq  = (const float*)d_in[1];
    const float* bq  = (const float*)d_in[2];
    const float* Wk  = (const float*)d_in[3];
    const float* bk  = (const float*)d_in[4];
    const float* Wv  = (const float*)d_in[5];
    const float* bv  = (const float*)d_in[6];
    const float* Wpq = (const float*)d_in[7];
    const float* bpq = (const float*)d_in[8];
    const float* Wpk = (const float*)d_in[9];
    const float* bpk = (const float*)d_in[10];
    const float* Wpv = (const float*)d_in[11];
    const float* bpv = (const float*)d_in[12];
    const float* Wd  = (const float*)d_in[13];
    const float* bd  = (const float*)d_in[14];
    float* out = (float*)d_out;

    cudaFuncSetAttribute(k_qkv_mma,    cudaFuncAttributeMaxDynamicSharedMemorySize, (int)SMEM_BYTES);
    cudaFuncSetAttribute(k_pool_mma,   cudaFuncAttributeMaxDynamicSharedMemorySize, (int)SMEM_BYTES);
    cudaFuncSetAttribute(k_logits_mma, cudaFuncAttributeMaxDynamicSharedMemorySize, (int)SMEM_BYTES);
    cudaFuncSetAttribute(k_av_mma,     cudaFuncAttributeMaxDynamicSharedMemorySize, (int)SMEM_BYTES);
    cudaFuncSetAttribute(k_out_mma,    cudaFuncAttributeMaxDynamicSharedMemorySize, (int)SMEM_BYTES);

    __nv_bfloat16 *xh, *xl, *wh0, *wl0, *ph0, *pl0, *wdh, *wdl;
    cudaGetSymbolAddress((void**)&xh,  g_xh);
    cudaGetSymbolAddress((void**)&xl,  g_xl);
    cudaGetSymbolAddress((void**)&wh0, g_Wh);
    cudaGetSymbolAddress((void**)&wl0, g_Wl);
    cudaGetSymbolAddress((void**)&ph0, g_Wph);
    cudaGetSymbolAddress((void**)&pl0, g_Wpl);
    cudaGetSymbolAddress((void**)&wdh, g_Wdh);
    cudaGetSymbolAddress((void**)&wdl, g_Wdl);
    __nv_bfloat16 *wh1 = wh0 + (size_t)QKVD * IND, *wh2 = wh1 + (size_t)QKVD * IND;
    __nv_bfloat16 *wl1 = wl0 + (size_t)QKVD * IND, *wl2 = wl1 + (size_t)QKVD * IND;
    __nv_bfloat16 *ph1 = ph0 + (size_t)HD * HD,    *ph2 = ph1 + (size_t)HD * HD;
    __nv_bfloat16 *pl1 = pl0 + (size_t)HD * HD,    *pl2 = pl1 + (size_t)HD * HD;

    auto cgrid = [](int n) { return (n + 255) / 256; };
    const int nW = QKVD * IND, nP = HD * HD, nX = MQ * IND, nD = IND * QKVD;

    k_conv<<<cgrid(nX), 256>>>(x,   xh,  xl,  nX);
    k_conv<<<cgrid(nW), 256>>>(Wq,  wh0, wl0, nW);
    k_conv<<<cgrid(nW), 256>>>(Wk,  wh1, wl1, nW);
    k_conv<<<cgrid(nW), 256>>>(Wv,  wh2, wl2, nW);
    k_conv<<<cgrid(nP), 256>>>(Wpq, ph0, pl0, nP);
    k_conv<<<cgrid(nP), 256>>>(Wpk, ph1, pl1, nP);
    k_conv<<<cgrid(nP), 256>>>(Wpv, ph2, pl2, nP);
    k_conv<<<cgrid(nD), 256>>>(Wd,  wdh, wdl, nD);

    dim3 t(256);
    k_qkv_mma<<<dim3(QKVD / 128, MP / 128, 3), t, SMEM_BYTES>>>(bq, bk, bv);
    k_cls2<<<cgrid(3 * BH * HD), 256>>>();
    k_pool_mma<<<dim3(HD / 128, BH * 8, 3), t, SMEM_BYTES>>>(bpq, bpk, bpv);
    k_logits_mma<<<dim3(LR / 128, LR / 128, BH), t, SMEM_BYTES>>>();
    k_softmax_mma<<<dim3(L, BH), 256>>>();
    k_av_mma<<<dim3(HD / 128, LR / 128, BH), t, SMEM_BYTES>>>();
    k_out_mma<<<dim3(IND / 128, MP / 128), t, SMEM_BYTES>>>(bd, out);
}

// round 12
// speedup vs baseline: 2.6622x; 1.0623x over previous
#include <cuda_runtime.h>
#include <cuda_bf16.h>
#include <cstdint>
#include <math.h>

// ============================================================================
// Problem constants
// ============================================================================
static constexpr int Bsz  = 4;
static constexpr int NH   = 8;
static constexpr int L    = 1025;
static constexpr int HD   = 512;
static constexpr int IND  = 512;
static constexpr int QKVD = 4096;
static constexpr int BH   = Bsz * NH;          // 32
static constexpr int MQ   = Bsz * L;           // 4100
static constexpr int MP   = 4224;              // padded M rows (33*128)
static constexpr int LR   = 1152;              // padded rows per (b,n) (9*128)
static constexpr int KA   = 1088;              // padded attn K cols (17*64)
static constexpr int LP   = 1028;              // fp32 logits row stride

// ============================================================================
// Global scratch (zero-initialized; pad regions never written)
// ============================================================================
__device__ __align__(16) __nv_bfloat16 g_xh[MP * IND];
__device__ __align__(16) __nv_bfloat16 g_xl[MP * IND];
__device__ __align__(16) __nv_bfloat16 g_Wh[3][QKVD * IND];
__device__ __align__(16) __nv_bfloat16 g_Wl[3][QKVD * IND];
__device__ __align__(16) __nv_bfloat16 g_Wph[3][HD * HD];
__device__ __align__(16) __nv_bfloat16 g_Wpl[3][HD * HD];
__device__ __align__(16) __nv_bfloat16 g_Wdh[IND * QKVD];
__device__ __align__(16) __nv_bfloat16 g_Wdl[IND * QKVD];
__device__ __align__(16) __nv_bfloat16 g_QKVh[3][(size_t)BH * L * HD];
__device__ __align__(16) __nv_bfloat16 g_QKVl[3][(size_t)BH * L * HD];
__device__ __align__(16) __nv_bfloat16 g_Ph[2][(size_t)BH * LR * HD];    // PQ, PK (token-major)
__device__ __align__(16) __nv_bfloat16 g_Pl[2][(size_t)BH * LR * HD];
__device__ __align__(16) __nv_bfloat16 g_PVth[(size_t)BH * HD * LR];     // PV transposed [hd][token]
__device__ __align__(16) __nv_bfloat16 g_PVtl[(size_t)BH * HD * LR];
__device__ __align__(16) float         g_logits[(size_t)BH * L * LP];
__device__ __align__(16) __nv_bfloat16 g_ah[(size_t)BH * LR * KA];
__device__ __align__(16) __nv_bfloat16 g_al[(size_t)BH * LR * KA];
__device__ __align__(16) __nv_bfloat16 g_sh[(size_t)MP * QKVD];
__device__ __align__(16) __nv_bfloat16 g_sl[(size_t)MP * QKVD];

// ============================================================================
// HMMA GEMM core v3: 128x128 CTA tile, 8 warps of 64x32.
// KC=32 k-chunks, 2-stage cp.async double buffer, R7-proven direct LDS frags.
// smem per stage: 4 tiles [128][AS2] bf16 (Ahi, Alo, Bhi, Blo).
// ============================================================================
#define AS2 40
#define KC  32
static constexpr uint32_t TILE_B = 128 * AS2 * 2;     // 10240
static constexpr uint32_t STG_B  = 4 * TILE_B;        // 40960
static constexpr size_t   SMEM_BYTES = 2 * STG_B;     // 81920

__device__ __forceinline__ uint32_t smem_u32(const void* p) {
    uint32_t a;
    asm("{ .reg .u64 t; cvta.to.shared.u64 t, %1; cvt.u32.u64 %0, t; }" : "=r"(a) : "l"(p));
    return a;
}

__device__ __forceinline__ void mma_bf16(float* d,
    uint32_t a0, uint32_t a1, uint32_t a2, uint32_t a3, uint32_t b0, uint32_t b1)
{
    asm volatile(
        "mma.sync.aligned.m16n8k16.row.col.f32.bf16.bf16.f32 "
        "{%0,%1,%2,%3}, {%4,%5,%6,%7}, {%8,%9}, {%0,%1,%2,%3};"
        : "+f"(d[0]), "+f"(d[1]), "+f"(d[2]), "+f"(d[3])
        : "r"(a0), "r"(a1), "r"(a2), "r"(a3), "r"(b0), "r"(b1));
}

// async-copy one 128x32 bf16 tile (row stride `stride` elems) into smem tile
__device__ __forceinline__ void cpa_tile(uint32_t dst,
    const __nv_bfloat16* __restrict__ src, size_t stride, int tid)
{
#pragma unroll
    for (int j = 0; j < 2; j++) {
        int ci = tid + j * 256;              // 0..511
        int r = ci >> 2, c = (ci & 3) * 8;
        uint32_t d = dst + (uint32_t)(r * AS2 + c) * 2;
        const void* s = src + (size_t)r * stride + c;
        asm volatile("cp.async.cg.shared.global [%0], [%1], 16;" :: "r"(d), "l"(s));
    }
}

// A: [128 rows, K] K-major hi/lo.  B: [128 n-rows, K] K-major hi/lo.
__device__ __forceinline__ void gemm_core(char* smem, uint32_t sbase,
    const __nv_bfloat16* Ah, const __nv_bfloat16* Al, size_t sA,
    const __nv_bfloat16* Bh, const __nv_bfloat16* Bl, size_t sB,
    int kt, float acc[4][4][4])
{
    const int tid = threadIdx.x, lane = tid & 31, wid = tid >> 5;
    const int wm = wid >> 2, wn = wid & 3;
    const int rbase = wm * 64 + (lane >> 2);
    const int nbase = wn * 32 + (lane >> 2);
    const int kb = (lane & 3) * 2;

    // prologue: stage 0
    cpa_tile(sbase + 0 * TILE_B, Ah, sA, tid);
    cpa_tile(sbase + 1 * TILE_B, Al, sA, tid);
    cpa_tile(sbase + 2 * TILE_B, Bh, sB, tid);
    cpa_tile(sbase + 3 * TILE_B, Bl, sB, tid);
    asm volatile("cp.async.commit_group;" ::: "memory");

    for (int t = 0; t < kt; t++) {
        const int s = t & 1;
        if (t + 1 < kt) {
            uint32_t so = sbase + (uint32_t)(s ^ 1) * STG_B;
            int k0 = (t + 1) * KC;
            cpa_tile(so + 0 * TILE_B, Ah + k0, sA, tid);
            cpa_tile(so + 1 * TILE_B, Al + k0, sA, tid);
            cpa_tile(so + 2 * TILE_B, Bh + k0, sB, tid);
            cpa_tile(so + 3 * TILE_B, Bl + k0, sB, tid);
            asm volatile("cp.async.commit_group;" ::: "memory");
            asm volatile("cp.async.wait_group 1;" ::: "memory");
        } else {
            asm volatile("cp.async.wait_group 0;" ::: "memory");
        }
        __syncthreads();

        const __nv_bfloat16* sAh = (const __nv_bfloat16*)(smem + (size_t)s * STG_B);
        const __nv_bfloat16* sAl = sAh + 128 * AS2;
        const __nv_bfloat16* sBh = sAl + 128 * AS2;
        const __nv_bfloat16* sBl = sBh + 128 * AS2;

#pragma unroll
        for (int kk = 0; kk < 2; kk++) {
            const int k0 = kk * 16 + kb;
            uint32_t bhf[4][2], blf[4][2];
#pragma unroll
            for (int j = 0; j < 4; j++) {
                int n = nbase + j * 8;
                bhf[j][0] = *(const uint32_t*)(sBh + n * AS2 + k0);
                bhf[j][1] = *(const uint32_t*)(sBh + n * AS2 + k0 + 8);
                blf[j][0] = *(const uint32_t*)(sBl + n * AS2 + k0);
                blf[j][1] = *(const uint32_t*)(sBl + n * AS2 + k0 + 8);
            }
#pragma unroll
            for (int i = 0; i < 4; i++) {
                int r = rbase + i * 16;
                uint32_t ah0 = *(const uint32_t*)(sAh + r * AS2 + k0);
                uint32_t ah1 = *(const uint32_t*)(sAh + (r + 8) * AS2 + k0);
                uint32_t ah2 = *(const uint32_t*)(sAh + r * AS2 + k0 + 8);
                uint32_t ah3 = *(const uint32_t*)(sAh + (r + 8) * AS2 + k0 + 8);
                uint32_t al0 = *(const uint32_t*)(sAl + r * AS2 + k0);
                uint32_t al1 = *(const uint32_t*)(sAl + (r + 8) * AS2 + k0);
                uint32_t al2 = *(const uint32_t*)(sAl + r * AS2 + k0 + 8);
                uint32_t al3 = *(const uint32_t*)(sAl + (r + 8) * AS2 + k0 + 8);
#pragma unroll
                for (int j = 0; j < 4; j++) {
                    mma_bf16(acc[i][j], ah0, ah1, ah2, ah3, bhf[j][0], bhf[j][1]);
                    mma_bf16(acc[i][j], ah0, ah1, ah2, ah3, blf[j][0], blf[j][1]);
                    mma_bf16(acc[i][j], al0, al1, al2, al3, bhf[j][0], bhf[j][1]);
                }
            }
        }
        __syncthreads();
    }
}

__device__ __forceinline__ void split_bf(float v, __nv_bfloat16* hp, __nv_bfloat16* lp) {
    __nv_bfloat16 h = __float2bfloat16(v);
    *hp = h;
    *lp = __float2bfloat16(v - __bfloat162float(h));
}

// epilogue element coordinates: acc[i][j][p] -> row er0+i*16+(p>>1)*8, col ec0+j*8+(p&1)
#define EPI_SETUP() \
    const int lane = threadIdx.x & 31, wid_ = threadIdx.x >> 5; \
    const int wm = wid_ >> 2, wn = wid_ & 3; \
    const int er0 = wm * 64 + (lane >> 2); \
    const int ec0 = wn * 32 + (lane & 3) * 2;

// ============================================================================
// Fused conversion: fp32 -> bf16 hi/lo, 8 segments in one launch
// ============================================================================
struct ConvSeg { const float* s; __nv_bfloat16* h; __nv_bfloat16* l; int n4; };
struct ConvArgs { ConvSeg seg[8]; };

__global__ __launch_bounds__(256) void k_conv_all(ConvArgs a)
{
    ConvSeg sg = a.seg[blockIdx.y];
    int i = blockIdx.x * 256 + threadIdx.x;
    if (i >= sg.n4) return;
    float4 v = ((const float4*)sg.s)[i];
    __nv_bfloat16 h0, h1, h2, h3, l0, l1, l2, l3;
    split_bf(v.x, &h0, &l0); split_bf(v.y, &h1, &l1);
    split_bf(v.z, &h2, &l2); split_bf(v.w, &h3, &l3);
    ushort4 hv = make_ushort4(*(unsigned short*)&h0, *(unsigned short*)&h1,
                              *(unsigned short*)&h2, *(unsigned short*)&h3);
    ushort4 lv = make_ushort4(*(unsigned short*)&l0, *(unsigned short*)&l1,
                              *(unsigned short*)&l2, *(unsigned short*)&l3);
    *(ushort4*)(sg.h + (size_t)i * 4) = hv;
    *(ushort4*)(sg.l + (size_t)i * 4) = lv;
}

// ============================================================================
// QKV projection.  grid (32, 33, 3)
// ============================================================================
__global__ __launch_bounds__(256, 2) void k_qkv_mma(
    const float* __restrict__ bq, const float* __restrict__ bk, const float* __restrict__ bv)
{
    extern __shared__ char smem[];
    uint32_t sbase = smem_u32(smem);
    const int z = blockIdx.z;
    const int row0 = blockIdx.y * 128, col0 = blockIdx.x * 128;
    const float* bias = (z == 0) ? bq : (z == 1) ? bk : bv;

    float acc[4][4][4] = {};
    gemm_core(smem, sbase,
        g_xh + (size_t)row0 * IND, g_xl + (size_t)row0 * IND, IND,
        g_Wh[z] + (size_t)col0 * IND, g_Wl[z] + (size_t)col0 * IND, IND,
        IND / KC, acc);

    EPI_SETUP();
    __nv_bfloat16* oh = g_QKVh[z];
    __nv_bfloat16* ol = g_QKVl[z];
#pragma unroll
    for (int i = 0; i < 4; i++)
#pragma unroll
        for (int p2 = 0; p2 < 2; p2++) {
            int m = row0 + er0 + i * 16 + p2 * 8;
            if (m >= MQ) continue;
            int bb = m / L, l = m - bb * L;
#pragma unroll
            for (int j = 0; j < 4; j++)
#pragma unroll
                for (int p1 = 0; p1 < 2; p1++) {
                    int o = col0 + ec0 + j * 8 + p1;
                    int n = o >> 9, ch = o & 511;
                    float v = acc[i][j][p2 * 2 + p1] + bias[o];
                    size_t idx = (((size_t)(bb * NH + n)) * L + l) * HD + ch;
                    split_bf(v, &oh[idx], &ol[idx]);
                }
        }
}

// ============================================================================
// cls passthrough
// ============================================================================
__global__ __launch_bounds__(256) void k_cls2()
{
    int idx = blockIdx.x * 256 + threadIdx.x;
    if (idx >= 3 * BH * HD) return;
    int z = idx / (BH * HD), rem = idx % (BH * HD);
    int bn = rem / HD, c = rem % HD;
    size_t so = ((size_t)bn * L) * HD + c;
    if (z < 2) {
        size_t d = ((size_t)bn * LR) * HD + c;
        g_Ph[z][d] = g_QKVh[z][so];
        g_Pl[z][d] = g_QKVl[z][so];
    } else {
        size_t d = ((size_t)bn * HD + c) * LR;   // token 0
        g_PVth[d] = g_QKVh[2][so];
        g_PVtl[d] = g_QKVl[2][so];
    }
}

// ============================================================================
// Pooler GEMM.  grid (4, 256, 3); y = bn*8 + mt.  z==2 writes PV transposed.
// ============================================================================
__global__ __launch_bounds__(256, 2) void k_pool_mma(
    const float* __restrict__ bpq, const float* __restrict__ bpk, const float* __restrict__ bpv)
{
    extern __shared__ char smem[];
    uint32_t sbase = smem_u32(smem);
    const int z = blockIdx.z;
    const int bn = blockIdx.y >> 3, mt = blockIdx.y & 7;
    const int col0 = blockIdx.x * 128;
    const float* bias = (z == 0) ? bpq : (z == 1) ? bpk : bpv;

    size_t arow = ((size_t)bn * L + 1 + mt * 128) * HD;
    float acc[4][4][4] = {};
    gemm_core(smem, sbase,
        g_QKVh[z] + arow, g_QKVl[z] + arow, HD,
        g_Wph[z] + (size_t)col0 * HD, g_Wpl[z] + (size_t)col0 * HD, HD,
        HD / KC, acc);

    EPI_SETUP();
    const float LOG1E4_128 = 9.210340371976184f / 128.0f;
#pragma unroll
    for (int i = 0; i < 4; i++)
#pragma unroll
        for (int p2 = 0; p2 < 2; p2++) {
            int s = mt * 128 + er0 + i * 16 + p2 * 8;     // spatial token 0..1023
#pragma unroll
            for (int j = 0; j < 4; j++)
#pragma unroll
                for (int p1 = 0; p1 < 2; p1++) {
                    int o = col0 + ec0 + j * 8 + p1;
                    float v = acc[i][j][p2 * 2 + p1] + bias[o];
                    if (z == 0) {
                        int yg = s >> 5, xg = s & 31;
                        float omega = expf(-(float)(o & 127) * LOG1E4_128);
                        float e;
                        if (o < 128)      e = sinf((float)yg * omega);
                        else if (o < 256) e = cosf((float)yg * omega);
                        else if (o < 384) e = sinf((float)xg * omega);
                        else              e = cosf((float)xg * omega);
                        v += e;
                    }
                    if (z < 2) {
                        size_t idx = ((size_t)bn * LR + 1 + s) * HD + o;
                        split_bf(v, &g_Ph[z][idx], &g_Pl[z][idx]);
                    } else {
                        size_t idx = ((size_t)bn * HD + o) * LR + 1 + s;
                        split_bf(v, &g_PVth[idx], &g_PVtl[idx]);
                    }
                }
        }
}

// ============================================================================
// Logits = PQ * PK^T * scale.  grid (9, 9, 32)
// ============================================================================
__global__ __launch_bounds__(256, 2) void k_logits_mma()
{
    extern __shared__ char smem[];
    uint32_t sbase = smem_u32(smem);
    const int bn = blockIdx.z;
    const int row0 = blockIdx.y * 128, col0 = blockIdx.x * 128;

    size_t abase = ((size_t)bn * LR + row0) * HD;
    size_t bbase = ((size_t)bn * LR + col0) * HD;
    float acc[4][4][4] = {};
    gemm_core(smem, sbase,
        g_Ph[0] + abase, g_Pl[0] + abase, HD,
        g_Ph[1] + bbase, g_Pl[1] + bbase, HD,
        HD / KC, acc);

    EPI_SETUP();
    const float scale = 0.044194173824159216f;   // 1/sqrt(512)
    float* dstb = g_logits + (size_t)bn * L * LP;
#pragma unroll
    for (int i = 0; i < 4; i++)
#pragma unroll
        for (int p2 = 0; p2 < 2; p2++) {
            int q = row0 + er0 + i * 16 + p2 * 8;
            if (q >= L) continue;
            float* dst = dstb + (size_t)q * LP;
#pragma unroll
            for (int j = 0; j < 4; j++)
#pragma unroll
                for (int p1 = 0; p1 < 2; p1++) {
                    int k = col0 + ec0 + j * 8 + p1;
                    if (k < L) dst[k] = acc[i][j][p2 * 2 + p1] * scale;
                }
        }
}

// ============================================================================
// Softmax -> attn hi/lo bf16.  grid (1025, 32)
// ============================================================================
__global__ __launch_bounds__(256) void k_softmax_mma()
{
    const int bn = blockIdx.y, row = blockIdx.x;
    const float* p = g_logits + ((size_t)bn * L + row) * LP;
    __nv_bfloat16* oh = g_ah + ((size_t)bn * LR + row) * KA;
    __nv_bfloat16* ol = g_al + ((size_t)bn * LR + row) * KA;
    __shared__ float red[256];
    const int tid = threadIdx.x;

    float v[5];
#pragma unroll
    for (int i = 0; i < 4; i++) v[i] = p[tid + (i << 8)];
    v[4] = (tid == 0) ? p[1024] : -1e30f;

    float m = v[0];
#pragma unroll
    for (int i = 1; i < 5; i++) m = fmaxf(m, v[i]);
    red[tid] = m; __syncthreads();
    for (int s = 128; s > 0; s >>= 1) {
        if (tid < s) red[tid] = fmaxf(red[tid], red[tid + s]);
        __syncthreads();
    }
    m = red[0]; __syncthreads();

    float sum = 0.f;
#pragma unroll
    for (int i = 0; i < 5; i++) { v[i] = expf(v[i] - m); sum += v[i]; }
    red[tid] = sum; __syncthreads();
    for (int s = 128; s > 0; s >>= 1) {
        if (tid < s) red[tid] += red[tid + s];
        __syncthreads();
    }
    float inv = 1.f / red[0];

#pragma unroll
    for (int i = 0; i < 4; i++) {
        int k = tid + (i << 8);
        split_bf(v[i] * inv, &oh[k], &ol[k]);
    }
    if (tid == 0) split_bf(v[4] * inv, &oh[1024], &ol[1024]);
}

// ============================================================================
// AV GEMM + residual + restack.  grid (4, 9, 32)
// A = attn [row][k] (stride KA), B = PVt [hd][token] (stride LR)
// ============================================================================
__global__ __launch_bounds__(256, 2) void k_av_mma()
{
    extern __shared__ char smem[];
    uint32_t sbase = smem_u32(smem);
    const int bn = blockIdx.z;
    const int row0 = blockIdx.y * 128, col0 = blockIdx.x * 128;

    float acc[4][4][4] = {};
    gemm_core(smem, sbase,
        g_ah + ((size_t)bn * LR + row0) * KA, g_al + ((size_t)bn * LR + row0) * KA, KA,
        g_PVth + ((size_t)bn * HD + col0) * LR, g_PVtl + ((size_t)bn * HD + col0) * LR, LR,
        KA / KC, acc);

    EPI_SETUP();
    const int bb = bn >> 3, n = bn & 7;
#pragma unroll
    for (int i = 0; i < 4; i++)
#pragma unroll
        for (int p2 = 0; p2 < 2; p2++) {
            int l = row0 + er0 + i * 16 + p2 * 8;
            if (l >= L) continue;
            size_t qb = ((size_t)bn * L + l) * HD;
            size_t sb = ((size_t)(bb * L + l)) * QKVD + n * HD;
#pragma unroll
            for (int j = 0; j < 4; j++)
#pragma unroll
                for (int p1 = 0; p1 < 2; p1++) {
                    int c = col0 + ec0 + j * 8 + p1;
                    float v = acc[i][j][p2 * 2 + p1];
                    if (l > 0)
                        v += __bfloat162float(g_QKVh[0][qb + c]) + __bfloat162float(g_QKVl[0][qb + c]);
                    split_bf(v, &g_sh[sb + c], &g_sl[sb + c]);
                }
        }
}

// ============================================================================
// Output projection.  grid (4, 33)
// ============================================================================
__global__ __launch_bounds__(256, 2) void k_out_mma(
    const float* __restrict__ bd, float* __restrict__ out)
{
    extern __shared__ char smem[];
    uint32_t sbase = smem_u32(smem);
    const int row0 = blockIdx.y * 128, col0 = blockIdx.x * 128;

    float acc[4][4][4] = {};
    gemm_core(smem, sbase,
        g_sh + (size_t)row0 * QKVD, g_sl + (size_t)row0 * QKVD, QKVD,
        g_Wdh + (size_t)col0 * QKVD, g_Wdl + (size_t)col0 * QKVD, QKVD,
        QKVD / KC, acc);

    EPI_SETUP();
#pragma unroll
    for (int i = 0; i < 4; i++)
#pragma unroll
        for (int p2 = 0; p2 < 2; p2++) {
            int m = row0 + er0 + i * 16 + p2 * 8;
            if (m >= MQ) continue;
            float* dst = out + (size_t)m * IND;
#pragma unroll
            for (int j = 0; j < 4; j++)
#pragma unroll
                for (int p1 = 0; p1 < 2; p1++) {
                    int o = col0 + ec0 + j * 8 + p1;
                    dst[o] = acc[i][j][p2 * 2 + p1] + bd[o];
                }
        }
}

// ============================================================================
// Launch
// ============================================================================
extern "C" void kernel_launch(void* const* d_in, const int* in_sizes, int n_in,
                              void* d_out, int out_size)
{
    const float* x   = (const float*)d_in[0];
    const float* Wq  = (const float*)d_in[1];
    const float* bq  = (const float*)d_in[2];
    const float* Wk  = (const float*)d_in[3];
    const float* bk  = (const float*)d_in[4];
    const float* Wv  = (const float*)d_in[5];
    const float* bv  = (const float*)d_in[6];
    const float* Wpq = (const float*)d_in[7];
    const float* bpq = (const float*)d_in[8];
    const float* Wpk = (const float*)d_in[9];
    const float* bpk = (const float*)d_in[10];
    const float* Wpv = (const float*)d_in[11];
    const float* bpv = (const float*)d_in[12];
    const float* Wd  = (const float*)d_in[13];
    const float* bd  = (const float*)d_in[14];
    float* out = (float*)d_out;

    cudaFuncSetAttribute(k_qkv_mma,    cudaFuncAttributeMaxDynamicSharedMemorySize, (int)SMEM_BYTES);
    cudaFuncSetAttribute(k_pool_mma,   cudaFuncAttributeMaxDynamicSharedMemorySize, (int)SMEM_BYTES);
    cudaFuncSetAttribute(k_logits_mma, cudaFuncAttributeMaxDynamicSharedMemorySize, (int)SMEM_BYTES);
    cudaFuncSetAttribute(k_av_mma,     cudaFuncAttributeMaxDynamicSharedMemorySize, (int)SMEM_BYTES);
    cudaFuncSetAttribute(k_out_mma,    cudaFuncAttributeMaxDynamicSharedMemorySize, (int)SMEM_BYTES);

    __nv_bfloat16 *xh, *xl, *wh0, *wl0, *ph0, *pl0, *wdh, *wdl;
    cudaGetSymbolAddress((void**)&xh,  g_xh);
    cudaGetSymbolAddress((void**)&xl,  g_xl);
    cudaGetSymbolAddress((void**)&wh0, g_Wh);
    cudaGetSymbolAddress((void**)&wl0, g_Wl);
    cudaGetSymbolAddress((void**)&ph0, g_Wph);
    cudaGetSymbolAddress((void**)&pl0, g_Wpl);
    cudaGetSymbolAddress((void**)&wdh, g_Wdh);
    cudaGetSymbolAddress((void**)&wdl, g_Wdl);
    __nv_bfloat16 *wh1 = wh0 + (size_t)QKVD * IND, *wh2 = wh1 + (size_t)QKVD * IND;
    __nv_bfloat16 *wl1 = wl0 + (size_t)QKVD * IND, *wl2 = wl1 + (size_t)QKVD * IND;
    __nv_bfloat16 *ph1 = ph0 + (size_t)HD * HD,    *ph2 = ph1 + (size_t)HD * HD;
    __nv_bfloat16 *pl1 = pl0 + (size_t)HD * HD,    *pl2 = pl1 + (size_t)HD * HD;

    const int nW = QKVD * IND, nP = HD * HD, nX = MQ * IND, nD = IND * QKVD;

    ConvArgs ca;
    ca.seg[0] = { x,   xh,  xl,  nX / 4 };
    ca.seg[1] = { Wq,  wh0, wl0, nW / 4 };
    ca.seg[2] = { Wk,  wh1, wl1, nW / 4 };
    ca.seg[3] = { Wv,  wh2, wl2, nW / 4 };
    ca.seg[4] = { Wpq, ph0, pl0, nP / 4 };
    ca.seg[5] = { Wpk, ph1, pl1, nP / 4 };
    ca.seg[6] = { Wpv, ph2, pl2, nP / 4 };
    ca.seg[7] = { Wd,  wdh, wdl, nD / 4 };
    // BUGFIX (R8/R10 root cause): x is the LARGEST segment (4100*512 > 4096*512).
    // Using nW/4 here left the last 4 rows of x unconverted (zeros) -> rel_err 3e-2.
    int maxn4 = nX / 4;                       // 524800: true largest segment
    k_conv_all<<<dim3((maxn4 + 255) / 256, 8), 256>>>(ca);

    dim3 t(256);
    k_qkv_mma<<<dim3(QKVD / 128, MP / 128, 3), t, SMEM_BYTES>>>(bq, bk, bv);
    k_cls2<<<(3 * BH * HD + 255) / 256, 256>>>();
    k_pool_mma<<<dim3(HD / 128, BH * 8, 3), t, SMEM_BYTES>>>(bpq, bpk, bpv);
    k_logits_mma<<<dim3(LR / 128, LR / 128, BH), t, SMEM_BYTES>>>();
    k_softmax_mma<<<dim3(L, BH), 256>>>();
    k_av_mma<<<dim3(HD / 128, LR / 128, BH), t, SMEM_BYTES>>>();
    k_out_mma<<<dim3(IND / 128, MP / 128), t, SMEM_BYTES>>>(bd, out);
}